// round 2
// baseline (speedup 1.0000x reference)
#include <cuda_runtime.h>
#include <stdint.h>

#define IN_CH   128
#define OUT_CH  64
#define N_MAX   100000
#define E_MAX   1600000

// Scratch (device globals — no runtime allocation allowed)
__device__ float g_h[(size_t)N_MAX * OUT_CH];   // 25.6 MB: h = x @ W
__device__ float g_dinv[N_MAX];
__device__ int   g_deg[N_MAX];

// ---------------------------------------------------------------------------
// Degree pipeline
// ---------------------------------------------------------------------------
__global__ void deg_init_kernel(int n) {
    int i = blockIdx.x * blockDim.x + threadIdx.x;
    if (i < n) g_deg[i] = 1;  // self loop
}

__global__ void deg_count_kernel(const int* __restrict__ dst, int e) {
    int i = blockIdx.x * blockDim.x + threadIdx.x;
    if (i < e) atomicAdd(&g_deg[dst[i]], 1);
}

__global__ void dinv_kernel(int n) {
    int i = blockIdx.x * blockDim.x + threadIdx.x;
    if (i < n) g_dinv[i] = rsqrtf((float)g_deg[i]);
}

// ---------------------------------------------------------------------------
// GEMM: h = x @ W  (fp32, 64x64 tile per block, 4x4 per thread)
// Epilogue fuses the self-loop term: out[i] = h[i] * dinv[i]^2 (also
// initializes the poisoned output buffer).
// ---------------------------------------------------------------------------
__global__ __launch_bounds__(256, 4)
void gemm_kernel(const float* __restrict__ x, const float* __restrict__ W,
                 float* __restrict__ out, int n) {
    __shared__ float xs[64][33];      // +1 pad vs bank conflicts
    __shared__ float ws[32][OUT_CH];  // k-chunk x all 64 cols

    const int tx  = threadIdx.x;      // 0..15 -> 4 cols each
    const int ty  = threadIdx.y;      // 0..15 -> 4 rows each
    const int tid = ty * 16 + tx;
    const int row0 = blockIdx.x * 64;

    float acc[4][4];
#pragma unroll
    for (int i = 0; i < 4; i++)
#pragma unroll
        for (int j = 0; j < 4; j++) acc[i][j] = 0.0f;

    for (int kc = 0; kc < IN_CH; kc += 32) {
        // Load x tile: 64 rows x 32 k = 512 float4, 2 per thread
#pragma unroll
        for (int t = 0; t < 2; t++) {
            int li = tid + t * 256;     // 0..511
            int r  = li >> 3;           // 0..63
            int k4 = li & 7;            // float4 index within 32
            float4 v = make_float4(0.f, 0.f, 0.f, 0.f);
            if (row0 + r < n)
                v = *(const float4*)(x + (size_t)(row0 + r) * IN_CH + kc + k4 * 4);
            xs[r][k4 * 4 + 0] = v.x;
            xs[r][k4 * 4 + 1] = v.y;
            xs[r][k4 * 4 + 2] = v.z;
            xs[r][k4 * 4 + 3] = v.w;
        }
        // Load W tile: 32 k x 64 cols = 512 float4, 2 per thread
#pragma unroll
        for (int t = 0; t < 2; t++) {
            int li = tid + t * 256;
            int k  = li >> 4;           // 0..31
            int c4 = li & 15;           // 0..15
            *(float4*)&ws[k][c4 * 4] =
                *(const float4*)(W + (size_t)(kc + k) * OUT_CH + c4 * 4);
        }
        __syncthreads();

#pragma unroll
        for (int kk = 0; kk < 32; kk++) {
            float a0 = xs[ty * 4 + 0][kk];
            float a1 = xs[ty * 4 + 1][kk];
            float a2 = xs[ty * 4 + 2][kk];
            float a3 = xs[ty * 4 + 3][kk];
            float4 b = *(float4*)&ws[kk][tx * 4];
            acc[0][0] += a0 * b.x; acc[0][1] += a0 * b.y; acc[0][2] += a0 * b.z; acc[0][3] += a0 * b.w;
            acc[1][0] += a1 * b.x; acc[1][1] += a1 * b.y; acc[1][2] += a1 * b.z; acc[1][3] += a1 * b.w;
            acc[2][0] += a2 * b.x; acc[2][1] += a2 * b.y; acc[2][2] += a2 * b.z; acc[2][3] += a2 * b.w;
            acc[3][0] += a3 * b.x; acc[3][1] += a3 * b.y; acc[3][2] += a3 * b.z; acc[3][3] += a3 * b.w;
        }
        __syncthreads();
    }

    // Epilogue: write h, and seed out with the self-loop contribution
#pragma unroll
    for (int i = 0; i < 4; i++) {
        int r = row0 + ty * 4 + i;
        if (r < n) {
            float d  = g_dinv[r];
            float d2 = d * d;
            float4 hv = make_float4(acc[i][0], acc[i][1], acc[i][2], acc[i][3]);
            *(float4*)(g_h + (size_t)r * OUT_CH + tx * 4) = hv;
            float4 ov = make_float4(hv.x * d2, hv.y * d2, hv.z * d2, hv.w * d2);
            *(float4*)(out + (size_t)r * OUT_CH + tx * 4) = ov;
        }
    }
}

// ---------------------------------------------------------------------------
// Edge scatter: one thread per (edge, 4-channel chunk) -> 16 threads/edge.
// Vector reduction (red.global.add.v4.f32, sm_90+) — no return value, 4x
// fewer L2 atomic transactions than scalar atomicAdd.
// ---------------------------------------------------------------------------
__global__ __launch_bounds__(256)
void scatter_kernel(const int* __restrict__ src, const int* __restrict__ dst,
                    float* __restrict__ out, int e) {
    int idx = blockIdx.x * blockDim.x + threadIdx.x;
    int ei  = idx >> 4;
    if (ei >= e) return;
    int q = idx & 15;

    int r = src[ei];        // broadcast across 16 lanes (L1 hit)
    int c = dst[ei];
    float norm = g_dinv[r] * g_dinv[c];

    float4 v = *((const float4*)(g_h + (size_t)r * OUT_CH) + q);
    v.x *= norm; v.y *= norm; v.z *= norm; v.w *= norm;

    float* op = out + (size_t)c * OUT_CH + q * 4;
    asm volatile("red.global.add.v4.f32 [%0], {%1, %2, %3, %4};"
                 :: "l"(op), "f"(v.x), "f"(v.y), "f"(v.z), "f"(v.w)
                 : "memory");
}

// ---------------------------------------------------------------------------
// Finalize: out = relu(out + b), vectorized float4
// ---------------------------------------------------------------------------
__global__ void finalize_kernel(const float* __restrict__ b,
                                float* __restrict__ out, int n) {
    int idx = blockIdx.x * blockDim.x + threadIdx.x;
    if (idx >= n * (OUT_CH / 4)) return;
    int q = idx & 15;
    float4 v  = ((float4*)out)[idx];
    float4 bb = ((const float4*)b)[q];
    v.x = fmaxf(v.x + bb.x, 0.f);
    v.y = fmaxf(v.y + bb.y, 0.f);
    v.z = fmaxf(v.z + bb.z, 0.f);
    v.w = fmaxf(v.w + bb.w, 0.f);
    ((float4*)out)[idx] = v;
}

// ---------------------------------------------------------------------------
extern "C" void kernel_launch(void* const* d_in, const int* in_sizes, int n_in,
                              void* d_out, int out_size) {
    const float* x  = (const float*)d_in[0];
    const int*   ei = (const int*)d_in[1];
    const float* W  = (const float*)d_in[2];
    const float* b  = (const float*)d_in[3];
    float*       out = (float*)d_out;

    const int n = in_sizes[0] / IN_CH;   // 100000
    const int e = in_sizes[1] / 2;       // 1600000
    const int* src = ei;                 // edge_index[0]
    const int* dst = ei + e;             // edge_index[1]

    deg_init_kernel<<<(n + 255) / 256, 256>>>(n);
    deg_count_kernel<<<(e + 255) / 256, 256>>>(dst, e);
    dinv_kernel<<<(n + 255) / 256, 256>>>(n);

    dim3 tb(16, 16);
    gemm_kernel<<<(n + 63) / 64, tb>>>(x, W, out, n);

    long sc_threads = (long)e * 16;
    scatter_kernel<<<(int)((sc_threads + 255) / 256), 256>>>(src, dst, out, e);

    finalize_kernel<<<(n * (OUT_CH / 4) + 255) / 256, 256>>>(b, out, n);
}